// round 15
// baseline (speedup 1.0000x reference)
#include <cuda_runtime.h>

#define NN 100000
#define EE 1600000
#define FIN 128
#define HH 64
#define OUTF 32
#define NB_SCAN 98   // ceil(100000/1024)

typedef unsigned long long u64;

// ---------------- scratch (device globals; no allocation) ----------------
// g_deg starts zero (static init); scan1_k re-zeroes after consuming.
__device__ int   g_deg[2 * NN];
__device__ float g_h[NN * HH];
__device__ float g_o[NN * HH];
__device__ float g_asrc[NN];
__device__ float g_adst[NN];
__device__ int   g_rank[2 * EE];
__device__ int   g_rowptr_loc[2 * NN];   // block-local exclusive prefix
__device__ int   g_bsum[2 * 128];
__device__ int   g_csr_src[2 * EE];

// ---------------- f32x2 packed-FMA helpers ----------------
__device__ __forceinline__ u64 bcast2(float x) {
    u64 r; asm("mov.b64 %0, {%1, %1};" : "=l"(r) : "f"(x)); return r;
}
__device__ __forceinline__ void fma2(u64& d, u64 a, u64 b) {
    asm("fma.rn.f32x2 %0, %1, %2, %0;" : "+l"(d) : "l"(a), "l"(b));
}
__device__ __forceinline__ float2 unpack2(u64 v) {
    float2 r; asm("mov.b64 {%0, %1}, %2;" : "=f"(r.x), "=f"(r.y) : "l"(v)); return r;
}

// ---------------- GEMM + fused attention dots ----------------
// Tile: 128 rows x 64 cols, K-chunk 32. Warp g owns cols [8g, 8g+8);
// all B reads are warp-uniform (LDS broadcast). 4 rows x 8 cols per thread.
template <int K, bool RELU>
__global__ void __launch_bounds__(256) gemm_att(
        const float* __restrict__ X, const float* __restrict__ W,
        float* __restrict__ Y,
        const float* __restrict__ av_s, const float* __restrict__ av_d) {
    __shared__ float xs[32][132];
    __shared__ float ws[32][64];
    __shared__ float redp[8][128];
    __shared__ float redd[8][128];
    int tid = threadIdx.x;
    int tn = (tid & 31) * 4;
    int g  = tid >> 5;
    int tc = g * 8;
    int row0 = blockIdx.x * 128;

    u64 acc[4][4];
#pragma unroll
    for (int i = 0; i < 4; i++)
#pragma unroll
        for (int j = 0; j < 4; j++) acc[i][j] = 0ull;

    for (int k0 = 0; k0 < K; k0 += 32) {
        for (int idx = tid; idx < 128 * 32; idx += 256) {
            int r = idx >> 5, k = idx & 31;
            int row = row0 + r;
            float v = (row < NN) ? X[row * K + k0 + k] : 0.f;
            if (RELU) v = fmaxf(v, 0.f);
            xs[k][r] = v;
        }
        for (int idx = tid; idx < 32 * 64; idx += 256) {
            int k = idx >> 6, c = idx & 63;
            ws[k][c] = W[(k0 + k) * 64 + c];
        }
        __syncthreads();
#pragma unroll 8
        for (int kk = 0; kk < 32; ++kk) {
            float4 a = *(const float4*)&xs[kk][tn];
            ulonglong2 b0 = *(const ulonglong2*)&ws[kk][tc];
            ulonglong2 b1 = *(const ulonglong2*)&ws[kk][tc + 4];
            u64 A0 = bcast2(a.x), A1 = bcast2(a.y), A2 = bcast2(a.z), A3 = bcast2(a.w);
            fma2(acc[0][0], A0, b0.x); fma2(acc[0][1], A0, b0.y);
            fma2(acc[0][2], A0, b1.x); fma2(acc[0][3], A0, b1.y);
            fma2(acc[1][0], A1, b0.x); fma2(acc[1][1], A1, b0.y);
            fma2(acc[1][2], A1, b1.x); fma2(acc[1][3], A1, b1.y);
            fma2(acc[2][0], A2, b0.x); fma2(acc[2][1], A2, b0.y);
            fma2(acc[2][2], A2, b1.x); fma2(acc[2][3], A2, b1.y);
            fma2(acc[3][0], A3, b0.x); fma2(acc[3][1], A3, b0.y);
            fma2(acc[3][2], A3, b1.x); fma2(acc[3][3], A3, b1.y);
        }
        __syncthreads();
    }

    float avs[8], avd[8];
#pragma unroll
    for (int j = 0; j < 8; j++) { avs[j] = av_s[tc + j]; avd[j] = av_d[tc + j]; }

#pragma unroll
    for (int i = 0; i < 4; i++) {
        int row = row0 + tn + i;
        float c[8];
#pragma unroll
        for (int j = 0; j < 4; j++) {
            float2 p = unpack2(acc[i][j]);
            c[2 * j] = p.x; c[2 * j + 1] = p.y;
        }
        if (row < NN) {
            *(float4*)&Y[row * 64 + tc]     = make_float4(c[0], c[1], c[2], c[3]);
            *(float4*)&Y[row * 64 + tc + 4] = make_float4(c[4], c[5], c[6], c[7]);
        }
        float ps = 0.f, pd = 0.f;
#pragma unroll
        for (int j = 0; j < 8; j++) { ps += c[j] * avs[j]; pd += c[j] * avd[j]; }
        redp[g][tn + i] = ps;
        redd[g][tn + i] = pd;
    }
    __syncthreads();
    if (tid < 128) {
        int row = row0 + tid;
        float ps = 0.f, pd = 0.f;
#pragma unroll
        for (int c = 0; c < 8; c++) { ps += redp[c][tid]; pd += redd[c][tid]; }
        if (row < NN) { g_asrc[row] = ps; g_adst[row] = pd; }
    }
}

// ---------------- CSR build (rank-capture; atomic only in hist) --------------
__global__ void hist_k(const int* __restrict__ e, int L) {
    int i = blockIdx.x * blockDim.x + threadIdx.x;
    if (i < EE) {
        int d = e[EE + i];
        g_rank[L * EE + i] = atomicAdd(&g_deg[L * NN + d], 1);
    }
}
// scan1: block-local exclusive prefix + block sums; zeroes deg for next call.
__global__ void scan1_k(int L) {
    __shared__ int s[1024];
    int tid = threadIdx.x;
    int i = blockIdx.x * 1024 + tid;
    int v = (i < NN) ? g_deg[L * NN + i] : 0;
    if (i < NN) g_deg[L * NN + i] = 0;
    s[tid] = v;
    __syncthreads();
#pragma unroll
    for (int off = 1; off < 1024; off <<= 1) {
        int t = (tid >= off) ? s[tid - off] : 0;
        __syncthreads();
        s[tid] += t;
        __syncthreads();
    }
    if (i < NN) g_rowptr_loc[L * NN + i] = s[tid] - v;
    if (tid == 1023) g_bsum[L * 128 + blockIdx.x] = s[1023];
}
// exclusive prefix of g_bsum into sp[128] (all threads of a >=128-thread block)
__device__ __forceinline__ void block_prefix(int* sp, int L, int tid) {
    if (tid < 128) {
        int src = tid - 1;
        sp[tid] = (src >= 0 && src < NB_SCAN) ? g_bsum[L * 128 + src] : 0;
    }
    __syncthreads();
#pragma unroll
    for (int off = 1; off < 128; off <<= 1) {
        int t = 0;
        if (tid < 128 && tid >= off) t = sp[tid - off];
        __syncthreads();
        if (tid < 128) sp[tid] += t;
        __syncthreads();
    }
}
// scatter: atomic-free via captured ranks + in-block prefix of block sums
__global__ void scatter_k(const int* __restrict__ e, int L) {
    __shared__ int sp[128];
    int tid = threadIdx.x;
    block_prefix(sp, L, tid);
    int i = blockIdx.x * blockDim.x + tid;
    if (i < EE) {
        int d = e[EE + i];
        int pos = __ldg(&g_rowptr_loc[L * NN + d]) + sp[d >> 10] + g_rank[L * EE + i];
        g_csr_src[L * EE + pos] = e[i];
    }
}

// ---------------- fused segment softmax + aggregate (f32x2 accumulate) -------
template <bool FINAL>
__global__ void __launch_bounds__(256, 6) agg_k(
        const float* __restrict__ h, const float* __restrict__ bias,
        float* __restrict__ out, int L,
        const float* __restrict__ Wl, const float* __restrict__ bl) {
    __shared__ int sp[128];
    __shared__ float wsh[64 * 32];
    int tid = threadIdx.x;
    block_prefix(sp, L, tid);
    if (FINAL) {
        for (int i = tid; i < 64 * 32; i += 256) wsh[i] = Wl[i];
        __syncthreads();
    }
    int wid = tid >> 5, lane = tid & 31;
    int node = blockIdx.x * 8 + wid;     // grid is exact: NN/8 blocks
    const int* rl = g_rowptr_loc + L * NN;
    int start = __ldg(&rl[node]) + sp[node >> 10];
    int end = (node + 1 == NN) ? EE
              : __ldg(&rl[node + 1]) + sp[(node + 1) >> 10];
    const int* csr = g_csr_src + L * EE;

    int half = lane >> 4;
    int q = (lane & 15) * 4;
    float ad = g_adst[node];

    u64 ax = 0ull, az = 0ull;            // packed (x,y) and (z,w) accumulators
    float ssum = 0.f;
    for (int j0 = start; j0 < end; j0 += 32) {
        int j = j0 + lane;
        int s = 0; float w = 0.f;
        if (j < end) {
            s = csr[j];
            float e = __ldg(&g_asrc[s]) + ad;
            e = (e >= 0.f) ? e : 0.2f * e;
            w = __expf(e);
        }
        ssum += w;
        int cnt = min(32, end - j0);
        int p2 = 0;
        for (; p2 + 8 <= cnt; p2 += 8) {
            int e0 = p2 + half, e1 = p2 + 2 + half, e2 = p2 + 4 + half, e3 = p2 + 6 + half;
            float w0 = __shfl_sync(0xffffffffu, w, e0);
            int   s0 = __shfl_sync(0xffffffffu, s, e0);
            float w1 = __shfl_sync(0xffffffffu, w, e1);
            int   s1 = __shfl_sync(0xffffffffu, s, e1);
            float w2 = __shfl_sync(0xffffffffu, w, e2);
            int   s2 = __shfl_sync(0xffffffffu, s, e2);
            float w3 = __shfl_sync(0xffffffffu, w, e3);
            int   s3 = __shfl_sync(0xffffffffu, s, e3);
            ulonglong2 H0 = *(const ulonglong2*)(h + s0 * 64 + q);
            ulonglong2 H1 = *(const ulonglong2*)(h + s1 * 64 + q);
            ulonglong2 H2 = *(const ulonglong2*)(h + s2 * 64 + q);
            ulonglong2 H3 = *(const ulonglong2*)(h + s3 * 64 + q);
            u64 W0 = bcast2(w0), W1 = bcast2(w1), W2 = bcast2(w2), W3 = bcast2(w3);
            fma2(ax, W0, H0.x); fma2(az, W0, H0.y);
            fma2(ax, W1, H1.x); fma2(az, W1, H1.y);
            fma2(ax, W2, H2.x); fma2(az, W2, H2.y);
            fma2(ax, W3, H3.x); fma2(az, W3, H3.y);
        }
        for (; p2 < cnt; p2 += 2) {
            int ei = p2 + half;
            int eic = (ei < cnt) ? ei : (cnt - 1);
            float wc = __shfl_sync(0xffffffffu, w, eic);
            int   sc = __shfl_sync(0xffffffffu, s, eic);
            if (ei < cnt) {
                ulonglong2 Hv = *(const ulonglong2*)(h + sc * 64 + q);
                u64 Wc = bcast2(wc);
                fma2(ax, Wc, Hv.x); fma2(az, Wc, Hv.y);
            }
        }
    }
    float2 pxy = unpack2(ax), pzw = unpack2(az);
    float4 acc = make_float4(pxy.x, pxy.y, pzw.x, pzw.y);
    acc.x += __shfl_xor_sync(0xffffffffu, acc.x, 16);
    acc.y += __shfl_xor_sync(0xffffffffu, acc.y, 16);
    acc.z += __shfl_xor_sync(0xffffffffu, acc.z, 16);
    acc.w += __shfl_xor_sync(0xffffffffu, acc.w, 16);
#pragma unroll
    for (int off = 16; off; off >>= 1) ssum += __shfl_xor_sync(0xffffffffu, ssum, off);
    float inv = 1.0f / (ssum + 1e-16f);

    float4 b4 = *(const float4*)(bias + q);
    float4 o;
    o.x = acc.x * inv + b4.x; o.y = acc.y * inv + b4.y;
    o.z = acc.z * inv + b4.z; o.w = acc.w * inv + b4.w;

    if (!FINAL) {
        if (half == 0) *(float4*)(out + node * 64 + q) = o;
    } else {
        float oarr[4] = {o.x, o.y, o.z, o.w};
        float accl = __ldg(&bl[lane]);
#pragma unroll
        for (int k = 0; k < 64; k++) {
            float xk = __shfl_sync(0xffffffffu, oarr[k & 3], k >> 2);
            accl += xk * wsh[k * 32 + lane];
        }
        float mx = accl;
#pragma unroll
        for (int off = 16; off; off >>= 1) mx = fmaxf(mx, __shfl_xor_sync(0xffffffffu, mx, off));
        float ex = __expf(accl - mx);
        float sum = ex;
#pragma unroll
        for (int off = 16; off; off >>= 1) sum += __shfl_xor_sync(0xffffffffu, sum, off);
        out[node * 32 + lane] = accl - mx - __logf(sum);
    }
}

// ---------------- launch: per-graph 3-kernel chains; chain2 hides under agg1 --
extern "C" void kernel_launch(void* const* d_in, const int* in_sizes, int n_in,
                              void* d_out, int out_size) {
    const float* x    = (const float*)d_in[0];
    const int*   ei1  = (const int*)d_in[1];
    const int*   ei2  = (const int*)d_in[2];
    const float* W1   = (const float*)d_in[3];
    const float* as1  = (const float*)d_in[4];
    const float* ad1  = (const float*)d_in[5];
    const float* b1   = (const float*)d_in[6];
    const float* W2   = (const float*)d_in[7];
    const float* as2  = (const float*)d_in[8];
    const float* ad2  = (const float*)d_in[9];
    const float* b2   = (const float*)d_in[10];
    const float* Wlin = (const float*)d_in[11];
    const float* blin = (const float*)d_in[12];
    float* out = (float*)d_out;

    float *h, *o;
    cudaGetSymbolAddress((void**)&h, g_h);
    cudaGetSymbolAddress((void**)&o, g_o);

    static cudaStream_t s1 = nullptr;
    static cudaEvent_t ev_fork = nullptr, ev_csr1 = nullptr, ev_csr2 = nullptr;
    if (s1 == nullptr) {
        cudaStreamCreateWithFlags(&s1, cudaStreamNonBlocking);
        cudaEventCreateWithFlags(&ev_fork, cudaEventDisableTiming);
        cudaEventCreateWithFlags(&ev_csr1, cudaEventDisableTiming);
        cudaEventCreateWithFlags(&ev_csr2, cudaEventDisableTiming);
    }

    const int gemm_grid = (NN + 127) / 128;   // 782
    const int agg_grid  = NN / 8;             // 12500 (exact)
    const int egrid = EE / 256;

    cudaEventRecord(ev_fork, 0);
    cudaStreamWaitEvent(s1, ev_fork, 0);

    // chain1 (graph 1) on s1 — overlaps gemm1
    hist_k<<<egrid, 256, 0, s1>>>(ei1, 0);                                    // #1
    scan1_k<<<NB_SCAN, 1024, 0, s1>>>(0);                                     // #2
    scatter_k<<<egrid, 256, 0, s1>>>(ei1, 0);                                 // #3
    cudaEventRecord(ev_csr1, s1);

    // main: gemm1 executes from t0
    gemm_att<FIN, false><<<gemm_grid, 256>>>(x, W1, h, as1, ad1);             // #4 <- ncu
    cudaStreamWaitEvent(0, ev_csr1, 0);
    agg_k<false><<<agg_grid, 256>>>(h, b1, o, 0, nullptr, nullptr);           // #5

    // chain2 (graph 2) on s1 — executes under agg1 + gemm2
    hist_k<<<egrid, 256, 0, s1>>>(ei2, 1);                                    // #6
    scan1_k<<<NB_SCAN, 1024, 0, s1>>>(1);                                     // #7
    scatter_k<<<egrid, 256, 0, s1>>>(ei2, 1);                                 // #8
    cudaEventRecord(ev_csr2, s1);

    gemm_att<HH, true><<<gemm_grid, 256>>>(o, W2, h, as2, ad2);               // #9
    cudaStreamWaitEvent(0, ev_csr2, 0);
    agg_k<true><<<agg_grid, 256>>>(h, b2, out, 1, Wlin, blin);                // #10
}

// round 17
// speedup vs baseline: 1.0586x; 1.0586x over previous
#include <cuda_runtime.h>

#define NN 100000
#define EE 1600000
#define FIN 128
#define HH 64
#define OUTF 32
#define NB_SCAN 98   // ceil(100000/1024)
#define SPLIT 50048  // 391 gemm tiles * 128; divisible by 8 for agg blocks

typedef unsigned long long u64;

// ---------------- scratch (device globals; no allocation) ----------------
// g_deg starts zero (static init); scan1_k re-zeroes after consuming.
__device__ int   g_deg[2 * NN];
__device__ float g_h1[NN * HH];      // layer-1 gemm output
__device__ float g_h2[NN * HH];      // layer-2 gemm output (separate: no WAR with agg1b)
__device__ float g_o[NN * HH];
__device__ float g_asrc1[NN];
__device__ float g_adst1[NN];
__device__ float g_asrc2[NN];
__device__ float g_adst2[NN];
__device__ int   g_rowptr[2 * (NN + 1)];
__device__ int   g_cursor[2 * NN];
__device__ int   g_csr_src[2 * EE];
__device__ int   g_bsum[2 * 128];

// ---------------- f32x2 packed-FMA helpers ----------------
__device__ __forceinline__ u64 bcast2(float x) {
    u64 r; asm("mov.b64 %0, {%1, %1};" : "=l"(r) : "f"(x)); return r;
}
__device__ __forceinline__ void fma2(u64& d, u64 a, u64 b) {
    asm("fma.rn.f32x2 %0, %1, %2, %0;" : "+l"(d) : "l"(a), "l"(b));
}
__device__ __forceinline__ float2 unpack2(u64 v) {
    float2 r; asm("mov.b64 {%0, %1}, %2;" : "=f"(r.x), "=f"(r.y) : "l"(v)); return r;
}

// ---------------- GEMM + fused attention dots ----------------
// Tile: 128 rows x 64 cols, K-chunk 32. Warp g owns cols [8g, 8g+8);
// all B reads are warp-uniform (LDS broadcast). 4 rows x 8 cols per thread.
template <int K, bool RELU>
__global__ void __launch_bounds__(256) gemm_att(
        const float* __restrict__ X, const float* __restrict__ W,
        float* __restrict__ Y,
        const float* __restrict__ av_s, const float* __restrict__ av_d,
        float* __restrict__ asrc, float* __restrict__ adst,
        int row_base) {
    __shared__ float xs[32][132];
    __shared__ float ws[32][64];
    __shared__ float redp[8][128];
    __shared__ float redd[8][128];
    int tid = threadIdx.x;
    int tn = (tid & 31) * 4;
    int g  = tid >> 5;
    int tc = g * 8;
    int row0 = row_base + blockIdx.x * 128;

    u64 acc[4][4];
#pragma unroll
    for (int i = 0; i < 4; i++)
#pragma unroll
        for (int j = 0; j < 4; j++) acc[i][j] = 0ull;

    for (int k0 = 0; k0 < K; k0 += 32) {
        for (int idx = tid; idx < 128 * 32; idx += 256) {
            int r = idx >> 5, k = idx & 31;
            int row = row0 + r;
            float v = (row < NN) ? X[row * K + k0 + k] : 0.f;
            if (RELU) v = fmaxf(v, 0.f);
            xs[k][r] = v;
        }
        for (int idx = tid; idx < 32 * 64; idx += 256) {
            int k = idx >> 6, c = idx & 63;
            ws[k][c] = W[(k0 + k) * 64 + c];
        }
        __syncthreads();
#pragma unroll 8
        for (int kk = 0; kk < 32; ++kk) {
            float4 a = *(const float4*)&xs[kk][tn];
            ulonglong2 b0 = *(const ulonglong2*)&ws[kk][tc];
            ulonglong2 b1 = *(const ulonglong2*)&ws[kk][tc + 4];
            u64 A0 = bcast2(a.x), A1 = bcast2(a.y), A2 = bcast2(a.z), A3 = bcast2(a.w);
            fma2(acc[0][0], A0, b0.x); fma2(acc[0][1], A0, b0.y);
            fma2(acc[0][2], A0, b1.x); fma2(acc[0][3], A0, b1.y);
            fma2(acc[1][0], A1, b0.x); fma2(acc[1][1], A1, b0.y);
            fma2(acc[1][2], A1, b1.x); fma2(acc[1][3], A1, b1.y);
            fma2(acc[2][0], A2, b0.x); fma2(acc[2][1], A2, b0.y);
            fma2(acc[2][2], A2, b1.x); fma2(acc[2][3], A2, b1.y);
            fma2(acc[3][0], A3, b0.x); fma2(acc[3][1], A3, b0.y);
            fma2(acc[3][2], A3, b1.x); fma2(acc[3][3], A3, b1.y);
        }
        __syncthreads();
    }

    float avs[8], avd[8];
#pragma unroll
    for (int j = 0; j < 8; j++) { avs[j] = av_s[tc + j]; avd[j] = av_d[tc + j]; }

#pragma unroll
    for (int i = 0; i < 4; i++) {
        int row = row0 + tn + i;
        float c[8];
#pragma unroll
        for (int j = 0; j < 4; j++) {
            float2 p = unpack2(acc[i][j]);
            c[2 * j] = p.x; c[2 * j + 1] = p.y;
        }
        if (row < NN) {
            *(float4*)&Y[row * 64 + tc]     = make_float4(c[0], c[1], c[2], c[3]);
            *(float4*)&Y[row * 64 + tc + 4] = make_float4(c[4], c[5], c[6], c[7]);
        }
        float ps = 0.f, pd = 0.f;
#pragma unroll
        for (int j = 0; j < 8; j++) { ps += c[j] * avs[j]; pd += c[j] * avd[j]; }
        redp[g][tn + i] = ps;
        redd[g][tn + i] = pd;
    }
    __syncthreads();
    if (tid < 128) {
        int row = row0 + tid;
        float ps = 0.f, pd = 0.f;
#pragma unroll
        for (int c = 0; c < 8; c++) { ps += redp[c][tid]; pd += redd[c][tid]; }
        if (row < NN) { asrc[row] = ps; adst[row] = pd; }
    }
}

// ---------------- CSR build (per-graph chains; R14 champion form) ----------
__global__ void hist_k(const int* __restrict__ e, int L) {
    int i = blockIdx.x * blockDim.x + threadIdx.x;
    if (i < EE) atomicAdd(&g_deg[L * NN + e[EE + i]], 1);
}
__global__ void scan1_k(int L) {
    __shared__ int s[1024];
    int tid = threadIdx.x;
    int i = blockIdx.x * 1024 + tid;
    int v = (i < NN) ? g_deg[L * NN + i] : 0;
    if (i < NN) g_deg[L * NN + i] = 0;      // reset for next call
    s[tid] = v;
    __syncthreads();
#pragma unroll
    for (int off = 1; off < 1024; off <<= 1) {
        int t = (tid >= off) ? s[tid - off] : 0;
        __syncthreads();
        s[tid] += t;
        __syncthreads();
    }
    if (i < NN) g_rowptr[L * (NN + 1) + i] = s[tid] - v;
    if (tid == 1023) g_bsum[L * 128 + blockIdx.x] = s[1023];
}
__global__ void scan23_k(int L) {
    __shared__ int bpart[128];
    __shared__ int base_s;
    int b = blockIdx.x;
    int tid = threadIdx.x;
    if (tid < 128) bpart[tid] = (tid < b) ? g_bsum[L * 128 + tid] : 0;
    __syncthreads();
    if (tid < 64) bpart[tid] += bpart[tid + 64];
    __syncthreads();
    if (tid < 32) {
        int v = bpart[tid] + bpart[tid + 32];
#pragma unroll
        for (int off = 16; off; off >>= 1) v += __shfl_xor_sync(0xffffffffu, v, off);
        if (tid == 0) base_s = v;
    }
    __syncthreads();
    int i = b * 1024 + tid;
    if (i < NN) {
        int r = g_rowptr[L * (NN + 1) + i] + base_s;
        g_rowptr[L * (NN + 1) + i] = r;
        g_cursor[L * NN + i] = r;
    }
    if (b == 0 && tid == 0) g_rowptr[L * (NN + 1) + NN] = EE;
}
__global__ void scatter_k(const int* __restrict__ e, int L) {
    int i = blockIdx.x * blockDim.x + threadIdx.x;
    if (i < EE) {
        int d = e[EE + i];
        int p = atomicAdd(&g_cursor[L * NN + d], 1);
        g_csr_src[L * EE + p] = e[i];
    }
}

// ---------------- fused segment softmax + aggregate (R14 champion form) ------
template <bool FINAL>
__global__ void __launch_bounds__(256, 6) agg_k(
        const float* __restrict__ h, const float* __restrict__ bias,
        float* __restrict__ out,
        const int* __restrict__ rowptr, const int* __restrict__ csr,
        const float* __restrict__ asrc, const float* __restrict__ adst,
        const float* __restrict__ Wl, const float* __restrict__ bl,
        int node_base) {
    __shared__ float wsh[64 * 32];
    if (FINAL) {
        for (int i = threadIdx.x; i < 64 * 32; i += 256) wsh[i] = Wl[i];
        __syncthreads();
    }
    int gw = node_base + ((blockIdx.x * blockDim.x + threadIdx.x) >> 5);
    int lane = threadIdx.x & 31;
    if (gw >= NN) return;
    int half = lane >> 4;
    int q = (lane & 15) * 4;
    int start = rowptr[gw];
    int end = rowptr[gw + 1];
    float ad = adst[gw];

    float4 acc = make_float4(0.f, 0.f, 0.f, 0.f);
    float ssum = 0.f;
    for (int j0 = start; j0 < end; j0 += 32) {
        int j = j0 + lane;
        int s = 0; float w = 0.f;
        if (j < end) {
            s = csr[j];
            float e = __ldg(&asrc[s]) + ad;
            e = (e >= 0.f) ? e : 0.2f * e;
            w = __expf(e);
        }
        ssum += w;
        int cnt = min(32, end - j0);
        int p2 = 0;
        for (; p2 + 8 <= cnt; p2 += 8) {
            int e0 = p2 + half, e1 = p2 + 2 + half, e2 = p2 + 4 + half, e3 = p2 + 6 + half;
            float w0 = __shfl_sync(0xffffffffu, w, e0);
            int   s0 = __shfl_sync(0xffffffffu, s, e0);
            float w1 = __shfl_sync(0xffffffffu, w, e1);
            int   s1 = __shfl_sync(0xffffffffu, s, e1);
            float w2 = __shfl_sync(0xffffffffu, w, e2);
            int   s2 = __shfl_sync(0xffffffffu, s, e2);
            float w3 = __shfl_sync(0xffffffffu, w, e3);
            int   s3 = __shfl_sync(0xffffffffu, s, e3);
            float4 h0 = *(const float4*)(h + s0 * 64 + q);
            float4 h1 = *(const float4*)(h + s1 * 64 + q);
            float4 h2 = *(const float4*)(h + s2 * 64 + q);
            float4 h3 = *(const float4*)(h + s3 * 64 + q);
            acc.x += w0 * h0.x + w1 * h1.x + w2 * h2.x + w3 * h3.x;
            acc.y += w0 * h0.y + w1 * h1.y + w2 * h2.y + w3 * h3.y;
            acc.z += w0 * h0.z + w1 * h1.z + w2 * h2.z + w3 * h3.z;
            acc.w += w0 * h0.w + w1 * h1.w + w2 * h2.w + w3 * h3.w;
        }
        for (; p2 < cnt; p2 += 2) {
            int ei = p2 + half;
            int eic = (ei < cnt) ? ei : (cnt - 1);
            float wc = __shfl_sync(0xffffffffu, w, eic);
            int   sc = __shfl_sync(0xffffffffu, s, eic);
            if (ei < cnt) {
                float4 hv = *(const float4*)(h + sc * 64 + q);
                acc.x += wc * hv.x; acc.y += wc * hv.y;
                acc.z += wc * hv.z; acc.w += wc * hv.w;
            }
        }
    }
    acc.x += __shfl_xor_sync(0xffffffffu, acc.x, 16);
    acc.y += __shfl_xor_sync(0xffffffffu, acc.y, 16);
    acc.z += __shfl_xor_sync(0xffffffffu, acc.z, 16);
    acc.w += __shfl_xor_sync(0xffffffffu, acc.w, 16);
#pragma unroll
    for (int off = 16; off; off >>= 1) ssum += __shfl_xor_sync(0xffffffffu, ssum, off);
    float inv = 1.0f / (ssum + 1e-16f);

    float4 b4 = *(const float4*)(bias + q);
    float4 o;
    o.x = acc.x * inv + b4.x; o.y = acc.y * inv + b4.y;
    o.z = acc.z * inv + b4.z; o.w = acc.w * inv + b4.w;

    if (!FINAL) {
        if (half == 0) *(float4*)(out + gw * 64 + q) = o;
    } else {
        float oarr[4] = {o.x, o.y, o.z, o.w};
        float accl = __ldg(&bl[lane]);
#pragma unroll
        for (int k = 0; k < 64; k++) {
            float xk = __shfl_sync(0xffffffffu, oarr[k & 3], k >> 2);
            accl += xk * wsh[k * 32 + lane];
        }
        float mx = accl;
#pragma unroll
        for (int off = 16; off; off >>= 1) mx = fmaxf(mx, __shfl_xor_sync(0xffffffffu, mx, off));
        float ex = __expf(accl - mx);
        float sum = ex;
#pragma unroll
        for (int off = 16; off; off >>= 1) sum += __shfl_xor_sync(0xffffffffu, sum, off);
        out[gw * 32 + lane] = accl - mx - __logf(sum);
    }
}

// ---------------- launch: R14 schedule + race-free agg1/gemm2 pipeline ------
extern "C" void kernel_launch(void* const* d_in, const int* in_sizes, int n_in,
                              void* d_out, int out_size) {
    const float* x    = (const float*)d_in[0];
    const int*   ei1  = (const int*)d_in[1];
    const int*   ei2  = (const int*)d_in[2];
    const float* W1   = (const float*)d_in[3];
    const float* as1  = (const float*)d_in[4];
    const float* ad1  = (const float*)d_in[5];
    const float* b1   = (const float*)d_in[6];
    const float* W2   = (const float*)d_in[7];
    const float* as2  = (const float*)d_in[8];
    const float* ad2  = (const float*)d_in[9];
    const float* b2   = (const float*)d_in[10];
    const float* Wlin = (const float*)d_in[11];
    const float* blin = (const float*)d_in[12];
    float* out = (float*)d_out;

    float *h1, *h2, *o, *asrc1, *adst1, *asrc2, *adst2;
    int *rowptr, *csr;
    cudaGetSymbolAddress((void**)&h1, g_h1);
    cudaGetSymbolAddress((void**)&h2, g_h2);
    cudaGetSymbolAddress((void**)&o, g_o);
    cudaGetSymbolAddress((void**)&asrc1, g_asrc1);
    cudaGetSymbolAddress((void**)&adst1, g_adst1);
    cudaGetSymbolAddress((void**)&asrc2, g_asrc2);
    cudaGetSymbolAddress((void**)&adst2, g_adst2);
    cudaGetSymbolAddress((void**)&rowptr, g_rowptr);
    cudaGetSymbolAddress((void**)&csr, g_csr_src);

    static cudaStream_t s1 = nullptr, s2 = nullptr;
    static cudaEvent_t ev_fork = nullptr, ev_csr1 = nullptr, ev_csr2 = nullptr,
                       ev_a1a = nullptr, ev_g2a = nullptr;
    if (s1 == nullptr) {
        cudaStreamCreateWithFlags(&s1, cudaStreamNonBlocking);
        cudaStreamCreateWithFlags(&s2, cudaStreamNonBlocking);
        cudaEventCreateWithFlags(&ev_fork, cudaEventDisableTiming);
        cudaEventCreateWithFlags(&ev_csr1, cudaEventDisableTiming);
        cudaEventCreateWithFlags(&ev_csr2, cudaEventDisableTiming);
        cudaEventCreateWithFlags(&ev_a1a, cudaEventDisableTiming);
        cudaEventCreateWithFlags(&ev_g2a, cudaEventDisableTiming);
    }

    const int gemm_grid  = (NN + 127) / 128;       // 782
    const int g2a_grid   = SPLIT / 128;            // 391
    const int g2b_grid   = gemm_grid - g2a_grid;   // 391
    const int a1a_grid   = SPLIT / 8;              // 6256
    const int a1b_grid   = (NN - SPLIT + 7) / 8;   // 6244
    const int agg_grid   = (NN + 7) / 8;           // 12500
    const int egrid      = EE / 256;

    cudaEventRecord(ev_fork, 0);
    cudaStreamWaitEvent(s1, ev_fork, 0);

    // chain1 (graph 1) on s1 — overlaps gemm1
    hist_k<<<egrid, 256, 0, s1>>>(ei1, 0);                                    // #1
    scan1_k<<<NB_SCAN, 1024, 0, s1>>>(0);                                     // #2
    scan23_k<<<NB_SCAN, 1024, 0, s1>>>(0);                                    // #3
    scatter_k<<<egrid, 256, 0, s1>>>(ei1, 0);                                 // #4
    cudaEventRecord(ev_csr1, s1);

    // main: gemm1 executes from t0 (writes h1/asrc1/adst1)
    gemm_att<FIN, false><<<gemm_grid, 256>>>(x, W1, h1, as1, ad1,
                                             asrc1, adst1, 0);                // #5
    cudaStreamWaitEvent(0, ev_csr1, 0);

    // agg1 first half -> gemm2a on s2 overlaps agg1 second half.
    // gemm2 writes h2/asrc2/adst2 (disjoint from agg1b's h1/asrc1/adst1 reads).
    agg_k<false><<<a1a_grid, 256>>>(h1, b1, o, rowptr, csr,
                                    asrc1, adst1, nullptr, nullptr, 0);       // #6
    cudaEventRecord(ev_a1a, 0);
    cudaStreamWaitEvent(s2, ev_a1a, 0);
    gemm_att<HH, true><<<g2a_grid, 256, 0, s2>>>(o, W2, h2, as2, ad2,
                                                 asrc2, adst2, 0);            // #7
    cudaEventRecord(ev_g2a, s2);

    agg_k<false><<<a1b_grid, 256>>>(h1, b1, o, rowptr, csr,
                                    asrc1, adst1, nullptr, nullptr, SPLIT);   // #8

    // chain2 (graph 2) on s1 — hides under agg1/gemm2
    hist_k<<<egrid, 256, 0, s1>>>(ei2, 1);                                    // #9
    scan1_k<<<NB_SCAN, 1024, 0, s1>>>(1);                                     // #10
    scan23_k<<<NB_SCAN, 1024, 0, s1>>>(1);                                    // #11
    scatter_k<<<egrid, 256, 0, s1>>>(ei2, 1);                                 // #12
    cudaEventRecord(ev_csr2, s1);

    // gemm2 second half on main, then final agg (reads h2/asrc2/adst2)
    gemm_att<HH, true><<<g2b_grid, 256>>>(o, W2, h2, as2, ad2,
                                          asrc2, adst2, SPLIT);               // #13
    cudaStreamWaitEvent(0, ev_g2a, 0);
    cudaStreamWaitEvent(0, ev_csr2, 0);
    agg_k<true><<<agg_grid, 256>>>(h2, b2, out, rowptr + (NN + 1), csr + EE,
                                   asrc2, adst2, Wlin, blin, 0);              // #14
}